// round 6
// baseline (speedup 1.0000x reference)
#include <cuda_runtime.h>
#include <cuda_bf16.h>
#include <cstdint>

#define BDIM 16384
#define CDIM 1024
#define DDIM 128
#define LOG2E 1.4426950408889634f

// ------------------------------- scratch -------------------------------
__device__ float s_theta[BDIM * DDIM];
__device__ float s_phi[BDIM * DDIM];
__device__ float s_g[BDIM * DDIM];

// A fragment-split buffers: [mtile][ktile][lane][{hi,lo} x 16B]
__device__ uint4 s_x0s[1024 * 64 * 32 * 2];
__device__ uint4 s_x1s[1024 * 64 * 32 * 2];
__device__ uint4 s_ys[1024 * 8 * 32 * 2];

__device__ __nv_bfloat16 s_gwh[DDIM * CDIM];
__device__ __nv_bfloat16 s_gwl[DDIM * CDIM];
__device__ __nv_bfloat16 s_thwh[DDIM * CDIM];
__device__ __nv_bfloat16 s_thwl[DDIM * CDIM];
__device__ __nv_bfloat16 s_phwh[DDIM * CDIM];
__device__ __nv_bfloat16 s_phwl[DDIM * CDIM];
__device__ __nv_bfloat16 s_Wwh[CDIM * DDIM];
__device__ __nv_bfloat16 s_Wwl[CDIM * DDIM];

// ------------------------------- helpers -------------------------------
__device__ __forceinline__ unsigned pkb(__nv_bfloat16 a, __nv_bfloat16 b) {
    return (unsigned)__bfloat16_as_ushort(a) | ((unsigned)__bfloat16_as_ushort(b) << 16);
}
__device__ __forceinline__ void ldsm4(uint32_t* r, uint32_t addr) {
    asm volatile("ldmatrix.sync.aligned.m8n8.x4.shared.b16 {%0,%1,%2,%3}, [%4];"
                 : "=r"(r[0]), "=r"(r[1]), "=r"(r[2]), "=r"(r[3]) : "r"(addr));
}
__device__ __forceinline__ void mma16816(float* c, const uint32_t* a, uint32_t b0, uint32_t b1) {
    asm volatile(
        "mma.sync.aligned.m16n8k16.row.col.f32.bf16.bf16.f32 "
        "{%0,%1,%2,%3}, {%4,%5,%6,%7}, {%8,%9}, {%0,%1,%2,%3};"
        : "+f"(c[0]), "+f"(c[1]), "+f"(c[2]), "+f"(c[3])
        : "r"(a[0]), "r"(a[1]), "r"(a[2]), "r"(a[3]), "r"(b0), "r"(b1));
}
__device__ __forceinline__ void cp16(uint32_t dst, const void* src) {
    asm volatile("cp.async.cg.shared.global [%0], [%1], 16;" :: "r"(dst), "l"(src));
}
#define CP_COMMIT() asm volatile("cp.async.commit_group;")
__device__ __forceinline__ float ex2f(float x) {
    float r; asm("ex2.approx.ftz.f32 %0, %1;" : "=f"(r) : "f"(x)); return r;
}
// degree-6 Taylor 2^f on [0,1): rel err ~1.7e-5 (runs on FMA/ALU pipes)
__device__ __forceinline__ float exp2poly(float x) {
    float i = floorf(x);
    i = fmaxf(i, -126.0f);
    float f = x - i;
    float p = fmaf(f, 1.5403530e-4f, 1.3333558e-3f);
    p = fmaf(f, p, 9.6181291e-3f);
    p = fmaf(f, p, 5.5504109e-2f);
    p = fmaf(f, p, 2.4022651e-1f);
    p = fmaf(f, p, 6.9314718e-1f);
    p = fmaf(f, p, 1.0f);
    return p * __int_as_float(((int)i + 127) << 23);
}

// ---------------- fused weight hi/lo split ----------------
__global__ void split4_kernel(const float* __restrict__ w0, const float* __restrict__ w1,
                              const float* __restrict__ w2, const float* __restrict__ w3) {
    int wsel = blockIdx.y;
    const float* in = wsel == 0 ? w0 : wsel == 1 ? w1 : wsel == 2 ? w2 : w3;
    __nv_bfloat16* hi = wsel == 0 ? s_gwh : wsel == 1 ? s_thwh : wsel == 2 ? s_phwh : s_Wwh;
    __nv_bfloat16* lo = wsel == 0 ? s_gwl : wsel == 1 ? s_thwl : wsel == 2 ? s_phwl : s_Wwl;
    const int n4 = DDIM * CDIM / 4;
    const float4* in4 = reinterpret_cast<const float4*>(in);
    uint2* hp = reinterpret_cast<uint2*>(hi);
    uint2* lp = reinterpret_cast<uint2*>(lo);
    for (int i = blockIdx.x * blockDim.x + threadIdx.x; i < n4; i += gridDim.x * blockDim.x) {
        float4 v = in4[i];
        __nv_bfloat16 a = __float2bfloat16(v.x), b = __float2bfloat16(v.y);
        __nv_bfloat16 c = __float2bfloat16(v.z), d = __float2bfloat16(v.w);
        __nv_bfloat16 e = __float2bfloat16(v.x - __bfloat162float(a));
        __nv_bfloat16 f = __float2bfloat16(v.y - __bfloat162float(b));
        __nv_bfloat16 g = __float2bfloat16(v.z - __bfloat162float(c));
        __nv_bfloat16 h = __float2bfloat16(v.w - __bfloat162float(d));
        hp[i] = make_uint2(pkb(a, b), pkb(c, d));
        lp[i] = make_uint2(pkb(e, f), pkb(g, h));
    }
}

// ---------------- A prepass: fp32 x -> hi/lo bf16 fragments ----------------
__global__ void __launch_bounds__(256)
prepass_kernel(const float* __restrict__ x0, const float* __restrict__ x1) {
    const float* x = blockIdx.y ? x1 : x0;
    uint4* dst = blockIdx.y ? s_x1s : s_x0s;
    int tile = blockIdx.x * 8 + (threadIdx.x >> 5);
    int lane = threadIdx.x & 31;
    int mt = tile >> 6, kt = tile & 63;
    int r0 = mt * 16 + (lane >> 2), c0 = kt * 16 + (lane & 3) * 2;
    const float* p = x + (size_t)r0 * CDIM + c0;
    float2 v0 = *reinterpret_cast<const float2*>(p);
    float2 v1 = *reinterpret_cast<const float2*>(p + 8 * CDIM);
    float2 v2 = *reinterpret_cast<const float2*>(p + 8);
    float2 v3 = *reinterpret_cast<const float2*>(p + 8 * CDIM + 8);
    __nv_bfloat16 h0 = __float2bfloat16(v0.x), h1 = __float2bfloat16(v0.y);
    __nv_bfloat16 h2 = __float2bfloat16(v1.x), h3 = __float2bfloat16(v1.y);
    __nv_bfloat16 h4 = __float2bfloat16(v2.x), h5 = __float2bfloat16(v2.y);
    __nv_bfloat16 h6 = __float2bfloat16(v3.x), h7 = __float2bfloat16(v3.y);
    __nv_bfloat16 l0 = __float2bfloat16(v0.x - __bfloat162float(h0));
    __nv_bfloat16 l1 = __float2bfloat16(v0.y - __bfloat162float(h1));
    __nv_bfloat16 l2 = __float2bfloat16(v1.x - __bfloat162float(h2));
    __nv_bfloat16 l3 = __float2bfloat16(v1.y - __bfloat162float(h3));
    __nv_bfloat16 l4 = __float2bfloat16(v2.x - __bfloat162float(h4));
    __nv_bfloat16 l5 = __float2bfloat16(v2.y - __bfloat162float(h5));
    __nv_bfloat16 l6 = __float2bfloat16(v3.x - __bfloat16_as_ushort(h6) * 0.f - __bfloat162float(h6));
    __nv_bfloat16 l7 = __float2bfloat16(v3.y - __bfloat162float(h7));
    l6 = __float2bfloat16(v3.x - __bfloat162float(h6));
    size_t idx = ((size_t)tile * 32 + lane) * 2;
    dst[idx]     = make_uint4(pkb(h0, h1), pkb(h2, h3), pkb(h4, h5), pkb(h6, h7));
    dst[idx + 1] = make_uint4(pkb(l0, l1), pkb(l2, l3), pkb(l4, l5), pkb(l6, l7));
}

// ---------------- split GEMM: 128x128 CTA, 512 thr, 16 warps (4m x 4n), warp 32x32 ----------------
#define SAP 40
#define WSTG 20480
#define GSMEM (4 * WSTG)

__device__ __forceinline__ void gemm_body(
    const uint4* __restrict__ As, int gmt0, int KT, int NC,
    const __nv_bfloat16* __restrict__ Wh, const __nv_bfloat16* __restrict__ Wl, int K,
    const float* __restrict__ bias, const float* __restrict__ resid,
    float* __restrict__ out, int ldo) {
    extern __shared__ unsigned char smem[];
    const int tid = threadIdx.x, lane = tid & 31, wid = tid >> 5;
    const int wm = (wid & 3) * 32, wn = (wid >> 2) * 32;
    const uint32_t sbase = (uint32_t)__cvta_generic_to_shared(smem);

    float acc[2][4][4];
#pragma unroll
    for (int a = 0; a < 2; a++)
#pragma unroll
        for (int b = 0; b < 4; b++)
#pragma unroll
            for (int c = 0; c < 4; c++) acc[a][b][c] = 0.f;

#define CPW(kc) do {                                                          \
        int _b = (kc) & 3, _kk = (kc) * 32;                                   \
        uint32_t _base = sbase + (uint32_t)_b * WSTG;                         \
        int _r = tid >> 2, _cc = tid & 3;                                     \
        uint32_t _d = _base + (uint32_t)(_r * SAP + _cc * 8) * 2;             \
        cp16(_d, Wh + (size_t)_r * K + _kk + _cc * 8);                        \
        cp16(_d + 10240, Wl + (size_t)_r * K + _kk + _cc * 8);                \
        CP_COMMIT();                                                          \
    } while (0)

    // A fragment base for this warp: rows [wm, wm+32) = mtiles gmt0+(wid&3)*2 +{0,1}
    const uint4* pA = As + ((size_t)(gmt0 + (wid & 3) * 2) * KT) * 64 + (size_t)lane * 2;
    const size_t mstr = (size_t)KT * 64;

    uint4 cur[4], nxt[4];
#define LDA(dst, kt) do {                                                     \
        (dst)[0] = pA[(size_t)(kt) * 64];                                     \
        (dst)[1] = pA[(size_t)(kt) * 64 + 1];                                 \
        (dst)[2] = pA[mstr + (size_t)(kt) * 64];                              \
        (dst)[3] = pA[mstr + (size_t)(kt) * 64 + 1];                          \
    } while (0)

    CPW(0); CPW(1); CPW(2);
    LDA(cur, 0);

    for (int kc = 0; kc < NC; kc++) {
        int w = NC - 1 - kc; if (w > 2) w = 2;
        if (w == 2)      asm volatile("cp.async.wait_group 2;");
        else if (w == 1) asm volatile("cp.async.wait_group 1;");
        else             asm volatile("cp.async.wait_group 0;");
        __syncthreads();
        if (kc + 3 < NC) CPW(kc + 3);

        const uint32_t wb = sbase + (uint32_t)(kc & 3) * WSTG;
#pragma unroll
        for (int ks = 0; ks < 2; ks++) {
            uint32_t wf0[4], wf1[4];
            const uint32_t w0off = (uint32_t)(((wn + (lane & 7) + ((lane >> 4) & 1) * 8) * SAP) +
                                              ks * 16 + ((lane >> 3) & 1) * 8) * 2;
            const uint32_t w1off = (uint32_t)(((wn + 16 + (lane & 7) + ((lane >> 4) & 1) * 8) * SAP) +
                                              ks * 16 + ((lane >> 3) & 1) * 8) * 2;
            ldsm4(wf0, wb + w0off);
            ldsm4(wf1, wb + w1off);
            int ktn = kc * 2 + ks + 1;
            if (ktn > KT - 1) ktn = KT - 1;
            LDA(nxt, ktn);
#pragma unroll
            for (int mt = 0; mt < 2; mt++) {
                const uint32_t* ah = reinterpret_cast<const uint32_t*>(&cur[2 * mt]);
                const uint32_t* al = reinterpret_cast<const uint32_t*>(&cur[2 * mt + 1]);
                mma16816(acc[mt][0], ah, wf0[0], wf0[1]);
                mma16816(acc[mt][1], ah, wf0[2], wf0[3]);
                mma16816(acc[mt][2], ah, wf1[0], wf1[1]);
                mma16816(acc[mt][3], ah, wf1[2], wf1[3]);
                mma16816(acc[mt][0], al, wf0[0], wf0[1]);
                mma16816(acc[mt][1], al, wf0[2], wf0[3]);
                mma16816(acc[mt][2], al, wf1[0], wf1[1]);
                mma16816(acc[mt][3], al, wf1[2], wf1[3]);
            }
            ldsm4(wf0, wb + 10240 + w0off);
            ldsm4(wf1, wb + 10240 + w1off);
#pragma unroll
            for (int mt = 0; mt < 2; mt++) {
                const uint32_t* ah = reinterpret_cast<const uint32_t*>(&cur[2 * mt]);
                mma16816(acc[mt][0], ah, wf0[0], wf0[1]);
                mma16816(acc[mt][1], ah, wf0[2], wf0[3]);
                mma16816(acc[mt][2], ah, wf1[0], wf1[1]);
                mma16816(acc[mt][3], ah, wf1[2], wf1[3]);
            }
#pragma unroll
            for (int i = 0; i < 4; i++) cur[i] = nxt[i];
        }
    }

#pragma unroll
    for (int mt = 0; mt < 2; mt++) {
        int r = wm + mt * 16 + (lane >> 2);
#pragma unroll
        for (int np = 0; np < 4; np++) {
            int c = wn + np * 8 + (lane & 3) * 2;
            float b0 = bias[c], b1 = bias[c + 1];
            float2 v0 = make_float2(acc[mt][np][0] + b0, acc[mt][np][1] + b1);
            float2 v1 = make_float2(acc[mt][np][2] + b0, acc[mt][np][3] + b1);
            size_t i0 = (size_t)r * ldo + c;
            size_t i1 = (size_t)(r + 8) * ldo + c;
            if (resid) {
                v0.x += resid[i0]; v0.y += resid[i0 + 1];
                v1.x += resid[i1]; v1.y += resid[i1 + 1];
            }
            *reinterpret_cast<float2*>(&out[i0]) = v0;
            *reinterpret_cast<float2*>(&out[i1]) = v1;
        }
    }
#undef CPW
#undef LDA
}

// grid (3, 128): x = {g, theta, phi}, y = row tile
__global__ void __launch_bounds__(512)
proj_gemm(const float* __restrict__ gb, const float* __restrict__ thb,
          const float* __restrict__ phb) {
    int bz = blockIdx.x;
    const uint4* As = bz == 0 ? s_x0s : s_x1s;
    const __nv_bfloat16* Wh = bz == 0 ? s_gwh : bz == 1 ? s_thwh : s_phwh;
    const __nv_bfloat16* Wl = bz == 0 ? s_gwl : bz == 1 ? s_thwl : s_phwl;
    const float* bias = bz == 0 ? gb : bz == 1 ? thb : phb;
    float* out = (bz == 0 ? s_g : bz == 1 ? s_theta : s_phi) + (size_t)blockIdx.y * 128 * DDIM;
    gemm_body(As, blockIdx.y * 8, 64, 32, Wh, Wl, CDIM, bias, nullptr, out, DDIM);
}

// grid (8, 128): x = n tile, y = row tile
__global__ void __launch_bounds__(512)
out_gemm(const float* __restrict__ Wb, const float* __restrict__ x0, float* __restrict__ out) {
    size_t n0 = (size_t)blockIdx.x * 128;
    size_t bm = (size_t)blockIdx.y * 128;
    gemm_body(s_ys, blockIdx.y * 8, 8, 4, s_Wwh + n0 * DDIM, s_Wwl + n0 * DDIM, DDIM,
              Wb + n0, x0 + bm * CDIM + n0, out + bm * CDIM + n0, CDIM);
}

// ---------------- rank-1 softmax attention; hybrid MUFU/FMA exp; y -> fragments ----------------
__global__ void __launch_bounds__(512)
attn16_kernel() {
    __shared__ float sth[16 * 128], sg[16 * 128], sph[16 * 128], sy[16 * 128];
    const int tid = threadIdx.x;
    const size_t base = (size_t)blockIdx.x * 16 * 128;
    reinterpret_cast<float4*>(sth)[tid] = reinterpret_cast<const float4*>(s_theta + base)[tid];
    reinterpret_cast<float4*>(sg)[tid]  = reinterpret_cast<const float4*>(s_g + base)[tid];
    reinterpret_cast<float4*>(sph)[tid] = reinterpret_cast<const float4*>(s_phi + base)[tid];
    __syncwarp();

    const int w = tid >> 5, l = tid & 31;
    const float* th = sth + w * 128;
    const float* gg = sg + w * 128;
    const float* ph = sph + w * 128;

    float a0 = th[l], a1 = th[l + 32], a2 = th[l + 64], a3 = th[l + 96];
    float mx = fmaxf(fmaxf(a0, a1), fmaxf(a2, a3));
    float mn = fminf(fminf(a0, a1), fminf(a2, a3));
#pragma unroll
    for (int off = 16; off >= 1; off >>= 1) {
        mx = fmaxf(mx, __shfl_xor_sync(0xffffffffu, mx, off));
        mn = fminf(mn, __shfl_xor_sync(0xffffffffu, mn, off));
    }
    float sc[4], m2n[4], num[4], den[4];
#pragma unroll
    for (int q = 0; q < 4; q++) {
        sc[q] = ph[l + 32 * q] * LOG2E;
        m2n[q] = -sc[q] * (sc[q] >= 0.f ? mx : mn);
        num[q] = 0.f; den[q] = 0.f;
    }
#pragma unroll 4
    for (int j = 0; j < 128; j += 4) {
        float4 tv = *reinterpret_cast<const float4*>(&th[j]);
        float4 gv = *reinterpret_cast<const float4*>(&gg[j]);
        float t_[4] = {tv.x, tv.y, tv.z, tv.w};
        float g_[4] = {gv.x, gv.y, gv.z, gv.w};
#pragma unroll
        for (int e = 0; e < 4; e++) {
#pragma unroll
            for (int q = 0; q < 4; q++) {
                const int idx = e * 4 + q;
                float arg = fmaf(sc[q], t_[e], m2n[q]);
                float ex = (idx == 1 || idx == 4 || idx == 7 || idx == 10 || idx == 13)
                               ? exp2poly(arg) : ex2f(arg);
                num[q] = fmaf(ex, g_[e], num[q]);
                den[q] += ex;
            }
        }
    }
#pragma unroll
    for (int q = 0; q < 4; q++) sy[w * 128 + l + 32 * q] = num[q] / den[q];
    __syncthreads();

    const int kt = tid >> 6, lane2 = (tid >> 1) & 31, part = tid & 1;
    const int r0 = lane2 >> 2, c0 = kt * 16 + (lane2 & 3) * 2;
    float v[8] = {sy[r0 * 128 + c0],       sy[r0 * 128 + c0 + 1],
                  sy[(r0 + 8) * 128 + c0], sy[(r0 + 8) * 128 + c0 + 1],
                  sy[r0 * 128 + c0 + 8],   sy[r0 * 128 + c0 + 9],
                  sy[(r0 + 8) * 128 + c0 + 8], sy[(r0 + 8) * 128 + c0 + 9]};
    __nv_bfloat16 h[8];
#pragma unroll
    for (int i = 0; i < 8; i++) h[i] = __float2bfloat16(v[i]);
    uint4 o;
    if (part == 0) {
        o = make_uint4(pkb(h[0], h[1]), pkb(h[2], h[3]), pkb(h[4], h[5]), pkb(h[6], h[7]));
    } else {
        __nv_bfloat16 lo[8];
#pragma unroll
        for (int i = 0; i < 8; i++) lo[i] = __float2bfloat16(v[i] - __bfloat162float(h[i]));
        o = make_uint4(pkb(lo[0], lo[1]), pkb(lo[2], lo[3]), pkb(lo[4], lo[5]), pkb(lo[6], lo[7]));
    }
    s_ys[((size_t)(blockIdx.x * 8 + kt) * 32 + lane2) * 2 + part] = o;
}

// ------------------------------- launch -------------------------------
extern "C" void kernel_launch(void* const* d_in, const int* in_sizes, int n_in,
                              void* d_out, int out_size) {
    const float* x0   = (const float*)d_in[0];
    const float* x1   = (const float*)d_in[1];
    const float* g_w  = (const float*)d_in[2];
    const float* g_b  = (const float*)d_in[3];
    const float* th_w = (const float*)d_in[4];
    const float* th_b = (const float*)d_in[5];
    const float* ph_w = (const float*)d_in[6];
    const float* ph_b = (const float*)d_in[7];
    const float* W_w  = (const float*)d_in[8];
    const float* W_b  = (const float*)d_in[9];
    float* out = (float*)d_out;

    cudaFuncSetAttribute(proj_gemm, cudaFuncAttributeMaxDynamicSharedMemorySize, GSMEM);
    cudaFuncSetAttribute(out_gemm, cudaFuncAttributeMaxDynamicSharedMemorySize, GSMEM);

    split4_kernel<<<dim3(32, 4), 256>>>(g_w, th_w, ph_w, W_w);
    prepass_kernel<<<dim3(8192, 2), 256>>>(x0, x1);

    proj_gemm<<<dim3(3, BDIM / 128), 512, GSMEM>>>(g_b, th_b, ph_b);

    attn16_kernel<<<BDIM / 16, 512>>>();

    out_gemm<<<dim3(8, BDIM / 128), 512, GSMEM>>>(W_b, x0, out);
}

// round 9
// speedup vs baseline: 2.2269x; 2.2269x over previous
#include <cuda_runtime.h>
#include <cuda_fp16.h>
#include <cstdint>

#define BDIM 16384
#define CDIM 1024
#define DDIM 128
#define LOG2E 1.4426950408889634f

// ------------------------------- scratch -------------------------------
__device__ float s_theta[BDIM * DDIM];
__device__ float s_phi[BDIM * DDIM];
__device__ float s_g[BDIM * DDIM];
__device__ float s_y[BDIM * DDIM];

__device__ __half s_gw[DDIM * CDIM];
__device__ __half s_thw[DDIM * CDIM];
__device__ __half s_phw[DDIM * CDIM];
__device__ __half s_Ww[CDIM * DDIM];

// ------------------------------- helpers -------------------------------
__device__ __forceinline__ unsigned pkh(__half a, __half b) {
    return (unsigned)__half_as_ushort(a) | ((unsigned)__half_as_ushort(b) << 16);
}
__device__ __forceinline__ void ldsm4(uint32_t* r, uint32_t addr) {
    asm volatile("ldmatrix.sync.aligned.m8n8.x4.shared.b16 {%0,%1,%2,%3}, [%4];"
                 : "=r"(r[0]), "=r"(r[1]), "=r"(r[2]), "=r"(r[3]) : "r"(addr));
}
__device__ __forceinline__ void mma16816(float* c, const uint32_t* a, uint32_t b0, uint32_t b1) {
    asm volatile(
        "mma.sync.aligned.m16n8k16.row.col.f32.f16.f16.f32 "
        "{%0,%1,%2,%3}, {%4,%5,%6,%7}, {%8,%9}, {%0,%1,%2,%3};"
        : "+f"(c[0]), "+f"(c[1]), "+f"(c[2]), "+f"(c[3])
        : "r"(a[0]), "r"(a[1]), "r"(a[2]), "r"(a[3]), "r"(b0), "r"(b1));
}
__device__ __forceinline__ void cp16(uint32_t dst, const void* src) {
    asm volatile("cp.async.cg.shared.global [%0], [%1], 16;" :: "r"(dst), "l"(src));
}
#define CP_COMMIT() asm volatile("cp.async.commit_group;")
#define CP_WAIT1()  asm volatile("cp.async.wait_group 1;")
__device__ __forceinline__ float ex2f(float x) {
    float r; asm("ex2.approx.ftz.f32 %0, %1;" : "=f"(r) : "f"(x)); return r;
}

// ---------------- fused weight fp16 convert (4 weights, one launch) ----------------
__global__ void split4_kernel(const float* __restrict__ w0, const float* __restrict__ w1,
                              const float* __restrict__ w2, const float* __restrict__ w3) {
    int wsel = blockIdx.y;
    const float* in = wsel == 0 ? w0 : wsel == 1 ? w1 : wsel == 2 ? w2 : w3;
    __half* hp = wsel == 0 ? s_gw : wsel == 1 ? s_thw : wsel == 2 ? s_phw : s_Ww;
    const int n4 = DDIM * CDIM / 4;
    const float4* in4 = reinterpret_cast<const float4*>(in);
    uint2* h2 = reinterpret_cast<uint2*>(hp);
    for (int i = blockIdx.x * blockDim.x + threadIdx.x; i < n4; i += gridDim.x * blockDim.x) {
        float4 v = in4[i];
        h2[i] = make_uint2(pkh(__float2half_rn(v.x), __float2half_rn(v.y)),
                           pkh(__float2half_rn(v.z), __float2half_rn(v.w)));
    }
}

// ---------------- fp16 GEMM: out[128,128] = A[128,K] @ W[128,K]^T + bias (+resid) ----------------
// R3-proven structure: CTA 128x128, BK=32, 256 thr, 8 warps (4m x 2n), warp tile 32x64.
// A fp32 from GMEM staged in regs -> fp16 STS; W fp16 double-buffered cp.async.
#define SAP 40
#define oW 10240u
#define GSMEM 30720

__device__ __forceinline__ void gemm_body(
    const float* __restrict__ A, int K, int NC,
    const __half* __restrict__ W,
    const float* __restrict__ bias, const float* __restrict__ resid,
    float* __restrict__ out, int ldo) {
    extern __shared__ unsigned char smem[];
    const int tid = threadIdx.x, lane = tid & 31, wid = tid >> 5;
    const int wm = (wid & 3) * 32, wn = (wid >> 2) * 64;
    const uint32_t sbase = (uint32_t)__cvta_generic_to_shared(smem);

    float acc[2][8][4];
#pragma unroll
    for (int a = 0; a < 2; a++)
#pragma unroll
        for (int b = 0; b < 8; b++)
#pragma unroll
            for (int c = 0; c < 4; c++) acc[a][b][c] = 0.f;

    float4 stage[4];
    // prologue: stage A chunk 0, cp.async W chunk 0
    {
#pragma unroll
        for (int i = 0; i < 4; i++) {
            int q = tid + 256 * i;
            stage[i] = *reinterpret_cast<const float4*>(
                &A[(size_t)(q >> 3) * K + (q & 7) * 4]);
        }
#pragma unroll
        for (int i = 0; i < 2; i++) {
            int q = tid + 256 * i;
            int r = q >> 2, cc = q & 3;
            cp16(sbase + oW + (uint32_t)(r * SAP + cc * 8) * 2,
                 W + (size_t)r * K + cc * 8);
        }
        CP_COMMIT();
    }

    for (int c = 0; c < NC; c++) {
        // STS: fp32 stage -> fp16 smem (chunk c)
#pragma unroll
        for (int i = 0; i < 4; i++) {
            int q = tid + 256 * i;
            int r = q >> 3, c4 = q & 7;
            float4 v = stage[i];
            *reinterpret_cast<uint2*>(smem + (size_t)(r * SAP + c4 * 4) * 2) =
                make_uint2(pkh(__float2half_rn(v.x), __float2half_rn(v.y)),
                           pkh(__float2half_rn(v.z), __float2half_rn(v.w)));
        }
        // prefetch chunk c+1
        if (c + 1 < NC) {
            int kk = (c + 1) * 32, buf = (c + 1) & 1;
#pragma unroll
            for (int i = 0; i < 4; i++) {
                int q = tid + 256 * i;
                stage[i] = *reinterpret_cast<const float4*>(
                    &A[(size_t)(q >> 3) * K + kk + (q & 7) * 4]);
            }
#pragma unroll
            for (int i = 0; i < 2; i++) {
                int q = tid + 256 * i;
                int r = q >> 2, cc = q & 3;
                cp16(sbase + oW + (uint32_t)buf * 10240u + (uint32_t)(r * SAP + cc * 8) * 2,
                     W + (size_t)r * K + kk + cc * 8);
            }
        }
        CP_COMMIT();
        CP_WAIT1();
        __syncthreads();

        const uint32_t wb = sbase + oW + (uint32_t)(c & 1) * 10240u;
#pragma unroll
        for (int ks = 0; ks < 2; ks++) {
            uint32_t ah[2][4], wf[4][4];
#pragma unroll
            for (int mt = 0; mt < 2; mt++) {
                uint32_t aoff = (uint32_t)((wm + mt * 16 + (lane & 15)) * SAP +
                                           ks * 16 + (lane >> 4) * 8) * 2;
                ldsm4(ah[mt], sbase + aoff);
            }
#pragma unroll
            for (int p = 0; p < 4; p++) {
                uint32_t woff = (uint32_t)((wn + p * 16 + (lane & 7) + ((lane >> 4) & 1) * 8) * SAP +
                                           ks * 16 + ((lane >> 3) & 1) * 8) * 2;
                ldsm4(wf[p], wb + woff);
            }
#pragma unroll
            for (int mt = 0; mt < 2; mt++)
#pragma unroll
                for (int p = 0; p < 4; p++) {
                    mma16816(acc[mt][2 * p], ah[mt], wf[p][0], wf[p][1]);
                    mma16816(acc[mt][2 * p + 1], ah[mt], wf[p][2], wf[p][3]);
                }
        }
        __syncthreads();
    }

    // epilogue
#pragma unroll
    for (int mt = 0; mt < 2; mt++) {
        int r0 = wm + mt * 16 + (lane >> 2);
#pragma unroll
        for (int nt = 0; nt < 8; nt++) {
            int ccol = wn + nt * 8 + (lane & 3) * 2;
            float2 v0 = make_float2(acc[mt][nt][0] + bias[ccol], acc[mt][nt][1] + bias[ccol + 1]);
            float2 v1 = make_float2(acc[mt][nt][2] + bias[ccol], acc[mt][nt][3] + bias[ccol + 1]);
            size_t i0 = (size_t)r0 * ldo + ccol;
            size_t i1 = (size_t)(r0 + 8) * ldo + ccol;
            if (resid) {
                v0.x += resid[i0]; v0.y += resid[i0 + 1];
                v1.x += resid[i1]; v1.y += resid[i1 + 1];
            }
            *reinterpret_cast<float2*>(&out[i0]) = v0;
            *reinterpret_cast<float2*>(&out[i1]) = v1;
        }
    }
}

// grid (3, 128): x = {g, theta, phi}, y = row tile
__global__ void __launch_bounds__(256)
proj_gemm(const float* __restrict__ x0, const float* __restrict__ x1,
          const float* __restrict__ gb, const float* __restrict__ thb,
          const float* __restrict__ phb) {
    int bz = blockIdx.x;
    size_t bm = (size_t)blockIdx.y * 128;
    const float* A = (bz == 0 ? x0 : x1) + bm * CDIM;
    const __half* W = bz == 0 ? s_gw : bz == 1 ? s_thw : s_phw;
    const float* bias = bz == 0 ? gb : bz == 1 ? thb : phb;
    float* out = (bz == 0 ? s_g : bz == 1 ? s_theta : s_phi) + bm * DDIM;
    gemm_body(A, CDIM, 32, W, bias, nullptr, out, DDIM);
}

// grid (8, 128): x = n tile, y = row tile
__global__ void __launch_bounds__(256)
out_gemm(const float* __restrict__ Wb, const float* __restrict__ x0, float* __restrict__ out) {
    size_t n0 = (size_t)blockIdx.x * 128;
    size_t bm = (size_t)blockIdx.y * 128;
    gemm_body(s_y + bm * DDIM, DDIM, 4, s_Ww + n0 * DDIM, Wb + n0,
              x0 + bm * CDIM + n0, out + bm * CDIM + n0, CDIM);
}

// ---------------- rank-1 softmax attention (R5's 69.9us shape, pure ex2f) ----------------
__global__ void __launch_bounds__(512)
attn16_kernel() {
    __shared__ float sth[16 * 128], sg[16 * 128], sph[16 * 128];
    const int tid = threadIdx.x;
    const size_t base = (size_t)blockIdx.x * 16 * 128;
    reinterpret_cast<float4*>(sth)[tid] = reinterpret_cast<const float4*>(s_theta + base)[tid];
    reinterpret_cast<float4*>(sg)[tid]  = reinterpret_cast<const float4*>(s_g + base)[tid];
    reinterpret_cast<float4*>(sph)[tid] = reinterpret_cast<const float4*>(s_phi + base)[tid];
    __syncwarp();

    const int w = tid >> 5, l = tid & 31;
    const float* th = sth + w * 128;
    const float* gg = sg + w * 128;
    const float* ph = sph + w * 128;

    float a0 = th[l], a1 = th[l + 32], a2 = th[l + 64], a3 = th[l + 96];
    float mx = fmaxf(fmaxf(a0, a1), fmaxf(a2, a3));
    float mn = fminf(fminf(a0, a1), fminf(a2, a3));
#pragma unroll
    for (int off = 16; off >= 1; off >>= 1) {
        mx = fmaxf(mx, __shfl_xor_sync(0xffffffffu, mx, off));
        mn = fminf(mn, __shfl_xor_sync(0xffffffffu, mn, off));
    }
    float sc[4], m2n[4], num[4], den[4];
#pragma unroll
    for (int q = 0; q < 4; q++) {
        sc[q] = ph[l + 32 * q] * LOG2E;
        m2n[q] = -sc[q] * (sc[q] >= 0.f ? mx : mn);
        num[q] = 0.f; den[q] = 0.f;
    }
#pragma unroll 8
    for (int j = 0; j < 128; j += 4) {
        float4 tv = *reinterpret_cast<const float4*>(&th[j]);
        float4 gv = *reinterpret_cast<const float4*>(&gg[j]);
        float t_[4] = {tv.x, tv.y, tv.z, tv.w};
        float g_[4] = {gv.x, gv.y, gv.z, gv.w};
#pragma unroll
        for (int e = 0; e < 4; e++) {
#pragma unroll
            for (int q = 0; q < 4; q++) {
                float ex = ex2f(fmaf(sc[q], t_[e], m2n[q]));
                num[q] = fmaf(ex, g_[e], num[q]);
                den[q] += ex;
            }
        }
    }
#pragma unroll
    for (int q = 0; q < 4; q++)
        s_y[base + (size_t)w * 128 + l + 32 * q] = num[q] / den[q];
}

// ------------------------------- launch -------------------------------
extern "C" void kernel_launch(void* const* d_in, const int* in_sizes, int n_in,
                              void* d_out, int out_size) {
    const float* x0   = (const float*)d_in[0];
    const float* x1   = (const float*)d_in[1];
    const float* g_w  = (const float*)d_in[2];
    const float* g_b  = (const float*)d_in[3];
    const float* th_w = (const float*)d_in[4];
    const float* th_b = (const float*)d_in[5];
    const float* ph_w = (const float*)d_in[6];
    const float* ph_b = (const float*)d_in[7];
    const float* W_w  = (const float*)d_in[8];
    const float* W_b  = (const float*)d_in[9];
    float* out = (float*)d_out;

    split4_kernel<<<dim3(32, 4), 256>>>(g_w, th_w, ph_w, W_w);

    proj_gemm<<<dim3(3, BDIM / 128), 256, GSMEM>>>(x0, x1, g_b, th_b, ph_b);

    attn16_kernel<<<BDIM / 16, 512>>>();

    out_gemm<<<dim3(8, BDIM / 128), 256, GSMEM>>>(W_b, x0, out);
}

// round 10
// speedup vs baseline: 2.5066x; 1.1256x over previous
#include <cuda_runtime.h>
#include <cuda_fp16.h>
#include <cstdint>

#define BDIM 16384
#define CDIM 1024
#define DDIM 128
#define LOG2E 1.4426950408889634f

// ------------------------------- scratch -------------------------------
__device__ float s_theta[BDIM * DDIM];
__device__ float s_phi[BDIM * DDIM];
__device__ float s_g[BDIM * DDIM];
__device__ float s_y[BDIM * DDIM];

__device__ __half s_gw[DDIM * CDIM];
__device__ __half s_thw[DDIM * CDIM];
__device__ __half s_phw[DDIM * CDIM];
__device__ __half s_Ww[CDIM * DDIM];

// ------------------------------- helpers -------------------------------
__device__ __forceinline__ unsigned pkh(__half a, __half b) {
    return (unsigned)__half_as_ushort(a) | ((unsigned)__half_as_ushort(b) << 16);
}
__device__ __forceinline__ void ldsm4(uint32_t* r, uint32_t addr) {
    asm volatile("ldmatrix.sync.aligned.m8n8.x4.shared.b16 {%0,%1,%2,%3}, [%4];"
                 : "=r"(r[0]), "=r"(r[1]), "=r"(r[2]), "=r"(r[3]) : "r"(addr));
}
__device__ __forceinline__ void mma16816(float* c, const uint32_t* a, uint32_t b0, uint32_t b1) {
    asm volatile(
        "mma.sync.aligned.m16n8k16.row.col.f32.f16.f16.f32 "
        "{%0,%1,%2,%3}, {%4,%5,%6,%7}, {%8,%9}, {%0,%1,%2,%3};"
        : "+f"(c[0]), "+f"(c[1]), "+f"(c[2]), "+f"(c[3])
        : "r"(a[0]), "r"(a[1]), "r"(a[2]), "r"(a[3]), "r"(b0), "r"(b1));
}
__device__ __forceinline__ void cp16(uint32_t dst, const void* src) {
    asm volatile("cp.async.cg.shared.global [%0], [%1], 16;" :: "r"(dst), "l"(src));
}
#define CP_COMMIT() asm volatile("cp.async.commit_group;")
#define CP_WAIT1()  asm volatile("cp.async.wait_group 1;")
__device__ __forceinline__ float ex2f(float x) {
    float r; asm("ex2.approx.ftz.f32 %0, %1;" : "=f"(r) : "f"(x)); return r;
}

// ---------------- fused weight fp16 convert (4 weights, one launch) ----------------
__global__ void split4_kernel(const float* __restrict__ w0, const float* __restrict__ w1,
                              const float* __restrict__ w2, const float* __restrict__ w3) {
    int wsel = blockIdx.y;
    const float* in = wsel == 0 ? w0 : wsel == 1 ? w1 : wsel == 2 ? w2 : w3;
    __half* hp = wsel == 0 ? s_gw : wsel == 1 ? s_thw : wsel == 2 ? s_phw : s_Ww;
    const int n4 = DDIM * CDIM / 4;
    const float4* in4 = reinterpret_cast<const float4*>(in);
    uint2* h2 = reinterpret_cast<uint2*>(hp);
    for (int i = blockIdx.x * blockDim.x + threadIdx.x; i < n4; i += gridDim.x * blockDim.x) {
        float4 v = in4[i];
        h2[i] = make_uint2(pkh(__float2half_rn(v.x), __float2half_rn(v.y)),
                           pkh(__float2half_rn(v.z), __float2half_rn(v.w)));
    }
}

// ---------------- fp16 GEMM core pieces (R3/R9-proven tiling) ----------------
// CTA 128x128, BK=32, 256 thr, 8 warps (4m x 2n), warp tile 32x64.
#define SAP 40
#define oW 10240u
#define GSMEM 30720

__device__ __forceinline__ void gemm_mainloop(
    const float* __restrict__ A, int K, int NC,
    const __half* __restrict__ W, unsigned char* smem, float acc[2][8][4]) {
    const int tid = threadIdx.x, lane = tid & 31, wid = tid >> 5;
    const int wm = (wid & 3) * 32, wn = (wid >> 2) * 64;
    const uint32_t sbase = (uint32_t)__cvta_generic_to_shared(smem);

    float4 stage[4];
    {
#pragma unroll
        for (int i = 0; i < 4; i++) {
            int q = tid + 256 * i;
            stage[i] = *reinterpret_cast<const float4*>(
                &A[(size_t)(q >> 3) * K + (q & 7) * 4]);
        }
#pragma unroll
        for (int i = 0; i < 2; i++) {
            int q = tid + 256 * i;
            int r = q >> 2, cc = q & 3;
            cp16(sbase + oW + (uint32_t)(r * SAP + cc * 8) * 2,
                 W + (size_t)r * K + cc * 8);
        }
        CP_COMMIT();
    }

    for (int c = 0; c < NC; c++) {
#pragma unroll
        for (int i = 0; i < 4; i++) {
            int q = tid + 256 * i;
            int r = q >> 3, c4 = q & 7;
            float4 v = stage[i];
            *reinterpret_cast<uint2*>(smem + (size_t)(r * SAP + c4 * 4) * 2) =
                make_uint2(pkh(__float2half_rn(v.x), __float2half_rn(v.y)),
                           pkh(__float2half_rn(v.z), __float2half_rn(v.w)));
        }
        if (c + 1 < NC) {
            int kk = (c + 1) * 32, buf = (c + 1) & 1;
#pragma unroll
            for (int i = 0; i < 4; i++) {
                int q = tid + 256 * i;
                stage[i] = *reinterpret_cast<const float4*>(
                    &A[(size_t)(q >> 3) * K + kk + (q & 7) * 4]);
            }
#pragma unroll
            for (int i = 0; i < 2; i++) {
                int q = tid + 256 * i;
                int r = q >> 2, cc = q & 3;
                cp16(sbase + oW + (uint32_t)buf * 10240u + (uint32_t)(r * SAP + cc * 8) * 2,
                     W + (size_t)r * K + kk + cc * 8);
            }
        }
        CP_COMMIT();
        CP_WAIT1();
        __syncthreads();

        const uint32_t wb = sbase + oW + (uint32_t)(c & 1) * 10240u;
#pragma unroll
        for (int ks = 0; ks < 2; ks++) {
            uint32_t ah[2][4], wf[4][4];
#pragma unroll
            for (int mt = 0; mt < 2; mt++) {
                uint32_t aoff = (uint32_t)((wm + mt * 16 + (lane & 15)) * SAP +
                                           ks * 16 + (lane >> 4) * 8) * 2;
                ldsm4(ah[mt], sbase + aoff);
            }
#pragma unroll
            for (int p = 0; p < 4; p++) {
                uint32_t woff = (uint32_t)((wn + p * 16 + (lane & 7) + ((lane >> 4) & 1) * 8) * SAP +
                                           ks * 16 + ((lane >> 3) & 1) * 8) * 2;
                ldsm4(wf[p], wb + woff);
            }
#pragma unroll
            for (int mt = 0; mt < 2; mt++)
#pragma unroll
                for (int p = 0; p < 4; p++) {
                    mma16816(acc[mt][2 * p], ah[mt], wf[p][0], wf[p][1]);
                    mma16816(acc[mt][2 * p + 1], ah[mt], wf[p][2], wf[p][3]);
                }
        }
        __syncthreads();
    }
}

// grid (3, 128): x = {g, theta, phi}, y = row tile. Direct fragment epilogue
// (outputs go to L2-resident scratch; proj is compute-bound so this is hidden).
__global__ void __launch_bounds__(256)
proj_gemm(const float* __restrict__ x0, const float* __restrict__ x1,
          const float* __restrict__ gb, const float* __restrict__ thb,
          const float* __restrict__ phb) {
    extern __shared__ unsigned char smem[];
    int bz = blockIdx.x;
    size_t bm = (size_t)blockIdx.y * 128;
    const float* A = (bz == 0 ? x0 : x1) + bm * CDIM;
    const __half* W = bz == 0 ? s_gw : bz == 1 ? s_thw : s_phw;
    const float* bias = bz == 0 ? gb : bz == 1 ? thb : phb;
    float* out = (bz == 0 ? s_g : bz == 1 ? s_theta : s_phi) + bm * DDIM;

    float acc[2][8][4];
#pragma unroll
    for (int a = 0; a < 2; a++)
#pragma unroll
        for (int b = 0; b < 8; b++)
#pragma unroll
            for (int c = 0; c < 4; c++) acc[a][b][c] = 0.f;

    gemm_mainloop(A, CDIM, 32, W, smem, acc);

    const int lane = threadIdx.x & 31, wid = threadIdx.x >> 5;
    const int wm = (wid & 3) * 32, wn = (wid >> 2) * 64;
#pragma unroll
    for (int mt = 0; mt < 2; mt++) {
        int r0 = wm + mt * 16 + (lane >> 2);
#pragma unroll
        for (int nt = 0; nt < 8; nt++) {
            int ccol = wn + nt * 8 + (lane & 3) * 2;
            float2 v0 = make_float2(acc[mt][nt][0] + bias[ccol], acc[mt][nt][1] + bias[ccol + 1]);
            float2 v1 = make_float2(acc[mt][nt][2] + bias[ccol], acc[mt][nt][3] + bias[ccol + 1]);
            *reinterpret_cast<float2*>(&out[(size_t)r0 * DDIM + ccol]) = v0;
            *reinterpret_cast<float2*>(&out[(size_t)(r0 + 8) * DDIM + ccol]) = v1;
        }
    }
}

// ---------------- out GEMM: smem-staged coalesced epilogue, 2 CTAs/SM ----------------
#define EPS 132                       // stage row stride in floats (528B, 16B-aligned)
#define OUT_STAGE (20480u)            // stage starts after W double buffer
#define OUT_SMEM (20480 + 128 * EPS * 4)

__global__ void __launch_bounds__(256, 2)
out_gemm(const float* __restrict__ Wb, const float* __restrict__ x0, float* __restrict__ out) {
    extern __shared__ unsigned char smem[];
    size_t n0 = (size_t)blockIdx.x * 128;
    size_t bm = (size_t)blockIdx.y * 128;
    const float* A = s_y + bm * DDIM;
    const __half* W = s_Ww + n0 * DDIM;
    const float* resid = x0 + bm * CDIM + n0;
    float* outp = out + bm * CDIM + n0;
    const float* bias = Wb + n0;

    float acc[2][8][4];
#pragma unroll
    for (int a = 0; a < 2; a++)
#pragma unroll
        for (int b = 0; b < 8; b++)
#pragma unroll
            for (int c = 0; c < 4; c++) acc[a][b][c] = 0.f;

    gemm_mainloop(A, DDIM, 4, W, smem, acc);

    // stage accumulators to smem
    float* ep = reinterpret_cast<float*>(smem + OUT_STAGE);
    const int tid = threadIdx.x, lane = tid & 31, wid = tid >> 5;
    const int wm = (wid & 3) * 32, wn = (wid >> 2) * 64;
#pragma unroll
    for (int mt = 0; mt < 2; mt++) {
        int r0 = wm + mt * 16 + (lane >> 2);
#pragma unroll
        for (int nt = 0; nt < 8; nt++) {
            int ccol = wn + nt * 8 + (lane & 3) * 2;
            *reinterpret_cast<float2*>(&ep[r0 * EPS + ccol]) =
                make_float2(acc[mt][nt][0], acc[mt][nt][1]);
            *reinterpret_cast<float2*>(&ep[(r0 + 8) * EPS + ccol]) =
                make_float2(acc[mt][nt][2], acc[mt][nt][3]);
        }
    }
    __syncthreads();

    // coalesced epilogue: bias + residual + store, float4 full-width
#pragma unroll
    for (int i = 0; i < 16; i++) {
        int idx = tid + 256 * i;           // 128 rows x 32 float4
        int row = idx >> 5, c4 = (idx & 31) * 4;
        float4 v = *reinterpret_cast<const float4*>(&ep[row * EPS + c4]);
        float4 bv = *reinterpret_cast<const float4*>(&bias[c4]);
        float4 rv = *reinterpret_cast<const float4*>(&resid[(size_t)row * CDIM + c4]);
        v.x += bv.x + rv.x; v.y += bv.y + rv.y;
        v.z += bv.z + rv.z; v.w += bv.w + rv.w;
        *reinterpret_cast<float4*>(&outp[(size_t)row * CDIM + c4]) = v;
    }
}

// ---------------- rank-1 softmax attention (measured 69.9us shape, pure ex2f) ----------------
__global__ void __launch_bounds__(512)
attn16_kernel() {
    __shared__ float sth[16 * 128], sg[16 * 128], sph[16 * 128];
    const int tid = threadIdx.x;
    const size_t base = (size_t)blockIdx.x * 16 * 128;
    reinterpret_cast<float4*>(sth)[tid] = reinterpret_cast<const float4*>(s_theta + base)[tid];
    reinterpret_cast<float4*>(sg)[tid]  = reinterpret_cast<const float4*>(s_g + base)[tid];
    reinterpret_cast<float4*>(sph)[tid] = reinterpret_cast<const float4*>(s_phi + base)[tid];
    __syncwarp();

    const int w = tid >> 5, l = tid & 31;
    const float* th = sth + w * 128;
    const float* gg = sg + w * 128;
    const float* ph = sph + w * 128;

    float a0 = th[l], a1 = th[l + 32], a2 = th[l + 64], a3 = th[l + 96];
    float mx = fmaxf(fmaxf(a0, a1), fmaxf(a2, a3));
    float mn = fminf(fminf(a0, a1), fminf(a2, a3));
#pragma unroll
    for (int off = 16; off >= 1; off >>= 1) {
        mx = fmaxf(mx, __shfl_xor_sync(0xffffffffu, mx, off));
        mn = fminf(mn, __shfl_xor_sync(0xffffffffu, mn, off));
    }
    float sc[4], m2n[4], num[4], den[4];
#pragma unroll
    for (int q = 0; q < 4; q++) {
        sc[q] = ph[l + 32 * q] * LOG2E;
        m2n[q] = -sc[q] * (sc[q] >= 0.f ? mx : mn);
        num[q] = 0.f; den[q] = 0.f;
    }
#pragma unroll 8
    for (int j = 0; j < 128; j += 4) {
        float4 tv = *reinterpret_cast<const float4*>(&th[j]);
        float4 gv = *reinterpret_cast<const float4*>(&gg[j]);
        float t_[4] = {tv.x, tv.y, tv.z, tv.w};
        float g_[4] = {gv.x, gv.y, gv.z, gv.w};
#pragma unroll
        for (int e = 0; e < 4; e++) {
#pragma unroll
            for (int q = 0; q < 4; q++) {
                float ex = ex2f(fmaf(sc[q], t_[e], m2n[q]));
                num[q] = fmaf(ex, g_[e], num[q]);
                den[q] += ex;
            }
        }
    }
#pragma unroll
    for (int q = 0; q < 4; q++)
        s_y[base + (size_t)w * 128 + l + 32 * q] = num[q] / den[q];
}

// ------------------------------- launch -------------------------------
extern "C" void kernel_launch(void* const* d_in, const int* in_sizes, int n_in,
                              void* d_out, int out_size) {
    const float* x0   = (const float*)d_in[0];
    const float* x1   = (const float*)d_in[1];
    const float* g_w  = (const float*)d_in[2];
    const float* g_b  = (const float*)d_in[3];
    const float* th_w = (const float*)d_in[4];
    const float* th_b = (const float*)d_in[5];
    const float* ph_w = (const float*)d_in[6];
    const float* ph_b = (const float*)d_in[7];
    const float* W_w  = (const float*)d_in[8];
    const float* W_b  = (const float*)d_in[9];
    float* out = (float*)d_out;

    cudaFuncSetAttribute(out_gemm, cudaFuncAttributeMaxDynamicSharedMemorySize, OUT_SMEM);

    split4_kernel<<<dim3(32, 4), 256>>>(g_w, th_w, ph_w, W_w);

    proj_gemm<<<dim3(3, BDIM / 128), 256, GSMEM>>>(x0, x1, g_b, th_b, ph_b);

    attn16_kernel<<<BDIM / 16, 512>>>();

    out_gemm<<<dim3(8, BDIM / 128), 256, OUT_SMEM>>>(W_b, x0, out);
}